// round 5
// baseline (speedup 1.0000x reference)
#include <cuda_runtime.h>
#include <stdint.h>
#include <math.h>

#define Bb   16
#define Cc   128
#define Hh   64
#define Ww   64
#define HID  128
#define OC   512   // 4*HID
#define NCTA 128   // 16 clusters (one per batch) x 8 CTAs

// Scratch (device global: allocation-free per harness rules)
__device__ float g_zis[(size_t)Bb*OC*Hh*Ww];     // [b, o, h, w]  134 MB

// ---- packed f32x2 helpers (sm_103a) --------------------------------------
#define PACK2(d, lo, hi) asm("mov.b64 %0, {%1,%2};" : "=l"(d) : "f"(lo), "f"(hi))
#define FMA2(d, a, b, c) asm("fma.rn.f32x2 %0, %1, %2, %3;" : "=l"(d) : "l"(a), "l"(b), "l"(c))
#define UNPK2(lo, hi, s) asm("mov.b64 {%0,%1}, %2;" : "=f"(lo), "=f"(hi) : "l"(s))

__device__ __forceinline__ uint32_t smem_u32(const void* p) {
    uint32_t a;
    asm("{ .reg .u64 t; cvta.to.shared.u64 t, %1; cvt.u32.u64 %0, t; }" : "=r"(a) : "l"(p));
    return a;
}
__device__ __forceinline__ uint32_t mapa_u32(uint32_t addr, uint32_t rank) {
    uint32_t r;
    asm("mapa.shared::cluster.u32 %0, %1, %2;" : "=r"(r) : "r"(addr), "r"(rank));
    return r;
}

// ---------------------------------------------------------------------------
// Phase 1: masked input-to-state conv (taps k=0,1; k=2 masked away).
// grid (B*H, OC/64), block 256 = 16(w)x16(o), 4w x 4o per thread, o paired f32x2.
__global__ void kA_zis(const float* __restrict__ x,
                       const float* __restrict__ Wis,
                       const float* __restrict__ bis) {
    extern __shared__ float sm[];
    float* xs = sm;               // [c][64]
    float* w0 = sm + 8192;        // [c][o_local]
    float* w1 = w0 + 8192;

    int b  = blockIdx.x >> 6;
    int h  = blockIdx.x & 63;
    int o0 = blockIdx.y * 64;
    int tid = threadIdx.x;

    for (int idx = tid; idx < 8192; idx += 256)
        xs[idx] = x[(((size_t)b*Cc + (idx >> 6))*Hh + h)*Ww + (idx & 63)];

    {   // coalesced weight read, scatter taps 0,1 into [c][o_local]
        const float* wsrc = Wis + (size_t)o0 * (Cc*3);
        for (int idx = tid; idx < 64*Cc*3; idx += 256) {
            float v = wsrc[idx];
            int ol  = idx / (Cc*3);
            int rem = idx - ol*(Cc*3);
            int c   = rem / 3;
            int k   = rem - c*3;
            if (k == 0)      w0[c*64 + ol] = v;
            else if (k == 1) w1[c*64 + ol] = v;
        }
    }
    __syncthreads();

    int tx = tid & 15, ty = tid >> 4;
    int wb = tx * 4;

    unsigned long long acc[2][4];
#pragma unroll
    for (int jp = 0; jp < 2; ++jp)
#pragma unroll
        for (int i = 0; i < 4; ++i) acc[jp][i] = 0ull;

#pragma unroll 2
    for (int c = 0; c < 128; ++c) {
        const float* xr = &xs[c*64 + wb];
        float4 xv = *reinterpret_cast<const float4*>(xr);
        float xm1 = (wb == 0) ? 0.f : xr[-1];
        float hv[5] = {xm1, xv.x, xv.y, xv.z, xv.w};
        unsigned long long hp[5];
#pragma unroll
        for (int t = 0; t < 5; ++t) PACK2(hp[t], hv[t], hv[t]);
#pragma unroll
        for (int jp = 0; jp < 2; ++jp) {
            unsigned long long w0p = *reinterpret_cast<const unsigned long long*>(&w0[c*64 + ty*4 + 2*jp]);
            unsigned long long w1p = *reinterpret_cast<const unsigned long long*>(&w1[c*64 + ty*4 + 2*jp]);
#pragma unroll
            for (int i = 0; i < 4; ++i) {
                FMA2(acc[jp][i], w0p, hp[i],   acc[jp][i]);
                FMA2(acc[jp][i], w1p, hp[i+1], acc[jp][i]);
            }
        }
    }

#pragma unroll
    for (int jp = 0; jp < 2; ++jp) {
        float lo[4], hi[4];
#pragma unroll
        for (int i = 0; i < 4; ++i) UNPK2(lo[i], hi[i], acc[jp][i]);
        int oA = o0 + ty*4 + 2*jp;
        float bA = bis[oA], bB = bis[oA+1];
        float4 rA = {lo[0]+bA, lo[1]+bA, lo[2]+bA, lo[3]+bA};
        float4 rB = {hi[0]+bB, hi[1]+bB, hi[2]+bB, hi[3]+bB};
        *reinterpret_cast<float4*>(&g_zis[(((size_t)b*OC + oA  )*Hh + h)*Ww + wb]) = rA;
        *reinterpret_cast<float4*>(&g_zis[(((size_t)b*OC + oA+1)*Hh + h)*Ww + wb]) = rB;
    }
}

// ---------------------------------------------------------------------------
// Phase 2: persistent fused recurrence. One cluster of 8 CTAs per batch b.
// CTA (b, hb) owns o-channels { g*128 + hb*16 + l }, computes gates for hid
// channels hb*16..hb*16+15, and pushes its h row into all 8 cluster CTAs'
// smem via DSMEM. Double-buffered hs -> one cluster.sync per row.
// hs layout: stride 72 floats per channel, h[w] at offset c*72 + 4 + w
// (so the v4 DSMEM store at w=wb is 16B-aligned; halos at +3 and +68 stay 0).
#define HSTR 72
#define HS1  (128*HSTR)
__global__ void __launch_bounds__(256, 1) __cluster_dims__(8, 1, 1)
kP_rows(const float* __restrict__ Wss,
        const float* __restrict__ bss,
        float* __restrict__ out) {
    extern __shared__ float sm[];
    float* wk   = sm;                    // [3][128][64]  24576 floats
    float* hs   = sm + 3*8192;           // [2][128][72]
    float* zbuf = hs + 2*HS1;            // [64][66]

    int b   = blockIdx.x >> 3;
    int hb  = blockIdx.x & 7;            // == cluster rank
    int tid = threadIdx.x;
    int tx  = tid & 15, ty = tid >> 4;
    int wb  = tx * 4;

    uint32_t smb = smem_u32(sm);

    // Load W_ss once: o_local = g*16 + l  ->  global o = g*128 + hb*16 + l
    for (int idx = tid; idx < 64*HID*3; idx += 256) {
        int ol  = idx / (HID*3);
        int rem = idx - ol*(HID*3);
        int g   = ol >> 4, l = ol & 15;
        int o   = g*128 + hb*16 + l;
        float v = Wss[(size_t)o*(HID*3) + rem];
        int c = rem / 3, k = rem - c*3;
        wk[k*8192 + c*64 + ol] = v;
    }
    // zero both h buffers (row0 h_prev = 0; halo columns stay 0 forever)
    for (int idx = tid; idx < 2*HS1; idx += 256) hs[idx] = 0.f;

    float sbv[4];
#pragma unroll
    for (int g = 0; g < 4; ++g) sbv[g] = bss[g*128 + hb*16 + ty];

    float cst[4] = {0.f, 0.f, 0.f, 0.f};
    int chg = hb*16 + ty;

    const float* zisb = g_zis + (size_t)b*OC*Hh*Ww;

    __syncthreads();
    // peers' hs zeroing must complete before our row-0 DSMEM writes land there
    asm volatile("barrier.cluster.arrive.aligned;" ::: "memory");
    asm volatile("barrier.cluster.wait.aligned;"   ::: "memory");

    for (int r = 0; r < Hh; ++r) {
        // prefetch z_is for the gate phase (this thread: channel chg, w=wb..wb+3)
        float4 ziv[4];
#pragma unroll
        for (int g = 0; g < 4; ++g)
            ziv[g] = *reinterpret_cast<const float4*>(
                &zisb[(((size_t)(g*128 + hb*16 + ty))*Hh + r)*Ww + wb]);

        unsigned long long acc[2][4];
#pragma unroll
        for (int jp = 0; jp < 2; ++jp)
#pragma unroll
            for (int i = 0; i < 4; ++i) acc[jp][i] = 0ull;

        if (r > 0) {
            const float* hsbuf = hs + (r & 1)*HS1;
#pragma unroll 2
            for (int c = 0; c < 128; ++c) {
                const float* hrow = &hsbuf[c*HSTR + wb];
                float  hm1 = hrow[3];                                    // h[wb-1]
                float4 h03 = *reinterpret_cast<const float4*>(hrow + 4); // h[wb..wb+3]
                float  h4  = hrow[8];                                    // h[wb+4]
                float hv[6] = {hm1, h03.x, h03.y, h03.z, h03.w, h4};
                unsigned long long hp[6];
#pragma unroll
                for (int t = 0; t < 6; ++t) PACK2(hp[t], hv[t], hv[t]);
#pragma unroll
                for (int k = 0; k < 3; ++k) {
#pragma unroll
                    for (int jp = 0; jp < 2; ++jp) {
                        unsigned long long wp = *reinterpret_cast<const unsigned long long*>(
                            &wk[k*8192 + c*64 + ty*4 + 2*jp]);
#pragma unroll
                        for (int i = 0; i < 4; ++i)
                            FMA2(acc[jp][i], wp, hp[i+k], acc[jp][i]);
                    }
                }
            }
        }

        // stage z_ss into zbuf[w][o_local]
#pragma unroll
        for (int jp = 0; jp < 2; ++jp)
#pragma unroll
            for (int i = 0; i < 4; ++i)
                *reinterpret_cast<unsigned long long*>(
                    &zbuf[(wb + i)*66 + ty*4 + 2*jp]) = acc[jp][i];
        __syncthreads();

        // gates for (ch = chg, w = wb..wb+3)
        float4 hres;
#pragma unroll
        for (int i = 0; i < 4; ++i) {
            int w = wb + i;
            float zi = zbuf[w*66 +  0 + ty] + sbv[0] + (&ziv[0].x)[i];
            float zf = zbuf[w*66 + 16 + ty] + sbv[1] + (&ziv[1].x)[i];
            float zo = zbuf[w*66 + 32 + ty] + sbv[2] + (&ziv[2].x)[i];
            float zg = zbuf[w*66 + 48 + ty] + sbv[3] + (&ziv[3].x)[i];
            float ig = 1.f / (1.f + __expf(-zi));
            float fg = 1.f / (1.f + __expf(-zf));
            float og = 1.f / (1.f + __expf(-zo));
            float gg = tanhf(zg);
            float cn = fg*cst[i] + ig*gg;
            cst[i] = cn;
            (&hres.x)[i] = og * tanhf(cn);
        }
        *reinterpret_cast<float4*>(&out[(((size_t)b*HID + chg)*Hh + r)*Ww + wb]) = hres;

        if (r < Hh - 1) {
            // push h row into all 8 cluster CTAs' next hs buffer via DSMEM
            // offset (floats): 3*8192 + buf*HS1 + chg*72 + 4 + wb  -> 16B aligned
            uint32_t dst = smb + (uint32_t)((3*8192 + ((r+1) & 1)*HS1 + chg*HSTR + 4 + wb) * 4);
#pragma unroll
            for (uint32_t pr = 0; pr < 8; ++pr) {
                uint32_t ra = mapa_u32(dst, pr);
                asm volatile("st.shared::cluster.v4.f32 [%0], {%1,%2,%3,%4};"
                             :: "r"(ra), "f"(hres.x), "f"(hres.y), "f"(hres.z), "f"(hres.w)
                             : "memory");
            }
            // release our writes / acquire peers' writes; also CTA-wide barrier
            asm volatile("barrier.cluster.arrive.aligned;" ::: "memory");
            asm volatile("barrier.cluster.wait.aligned;"   ::: "memory");
        }
    }
}

// ---------------------------------------------------------------------------
extern "C" void kernel_launch(void* const* d_in, const int* in_sizes, int n_in,
                              void* d_out, int out_size) {
    const float* x   = (const float*)d_in[0];
    const float* Wis = (const float*)d_in[1];
    const float* bis = (const float*)d_in[2];
    const float* Wss = (const float*)d_in[3];
    const float* bss = (const float*)d_in[4];
    float* out = (float*)d_out;

    const int SMEM_A = 3*8192*sizeof(float);                       // 98304
    const int SMEM_P = (3*8192 + 2*HS1 + 64*66)*sizeof(float);     // 188928
    cudaFuncSetAttribute(kA_zis,  cudaFuncAttributeMaxDynamicSharedMemorySize, SMEM_A);
    cudaFuncSetAttribute(kP_rows, cudaFuncAttributeMaxDynamicSharedMemorySize, SMEM_P);

    dim3 gA(Bb*Hh, OC/64);
    kA_zis<<<gA, 256, SMEM_A>>>(x, Wis, bis);

    kP_rows<<<NCTA, 256, SMEM_P>>>(Wss, bss, out);
}

// round 6
// speedup vs baseline: 1.3784x; 1.3784x over previous
#include <cuda_runtime.h>
#include <stdint.h>
#include <math.h>

#define Bb   16
#define Cc   128
#define Hh   64
#define Ww   64
#define HID  128
#define OC   512   // 4*HID
#define NCTA 128   // 16 b x 8 hid-blocks, all co-resident (<=148 SMs, 1 CTA/SM)

// Scratch (device globals: allocation-free per harness rules)
__device__ float    g_zis[(size_t)Bb*OC*Hh*Ww];   // [b, o, h, w]  134 MB
__device__ float    g_hbuf[2][Bb*HID*Ww];         // double-buffered hidden state
__device__ unsigned g_cnt[16*32];                 // per-batch barrier counters (128B apart)

// ---- packed f32x2 helpers (sm_103a) --------------------------------------
#define PACK2(d, lo, hi) asm("mov.b64 %0, {%1,%2};" : "=l"(d) : "f"(lo), "f"(hi))
#define FMA2(d, a, b, c) asm("fma.rn.f32x2 %0, %1, %2, %3;" : "=l"(d) : "l"(a), "l"(b), "l"(c))
#define UNPK2(lo, hi, s) asm("mov.b64 {%0,%1}, %2;" : "=f"(lo), "=f"(hi) : "l"(s))

__device__ __forceinline__ unsigned ld_acq_gpu(const unsigned* p) {
    unsigned v;
    asm volatile("ld.global.acquire.gpu.u32 %0, [%1];" : "=r"(v) : "l"(p) : "memory");
    return v;
}
__device__ __forceinline__ void red_rel_gpu(unsigned* p, unsigned v) {
    asm volatile("red.release.gpu.global.add.u32 [%0], %1;" :: "l"(p), "r"(v) : "memory");
}

// ---------------------------------------------------------------------------
__global__ void init_kernel() {
    int i = threadIdx.x;
    if (i < 16*32) g_cnt[i] = 0u;
}

// ---------------------------------------------------------------------------
// Phase 1: masked input-to-state conv (taps k=0,1; k=2 masked away).
// grid (B*H, OC/64), block 256 = 16(w)x16(o), 4w x 4o per thread, o paired f32x2.
__global__ void kA_zis(const float* __restrict__ x,
                       const float* __restrict__ Wis,
                       const float* __restrict__ bis) {
    extern __shared__ float sm[];
    float* xs = sm;               // [c][64]
    float* w0 = sm + 8192;        // [c][o_local]
    float* w1 = w0 + 8192;

    int b  = blockIdx.x >> 6;
    int h  = blockIdx.x & 63;
    int o0 = blockIdx.y * 64;
    int tid = threadIdx.x;

    for (int idx = tid; idx < 8192; idx += 256)
        xs[idx] = x[(((size_t)b*Cc + (idx >> 6))*Hh + h)*Ww + (idx & 63)];

    {   // coalesced weight read, scatter taps 0,1 into [c][o_local]
        const float* wsrc = Wis + (size_t)o0 * (Cc*3);
        for (int idx = tid; idx < 64*Cc*3; idx += 256) {
            float v = wsrc[idx];
            int ol  = idx / (Cc*3);
            int rem = idx - ol*(Cc*3);
            int c   = rem / 3;
            int k   = rem - c*3;
            if (k == 0)      w0[c*64 + ol] = v;
            else if (k == 1) w1[c*64 + ol] = v;
        }
    }
    __syncthreads();

    int tx = tid & 15, ty = tid >> 4;
    int wb = tx * 4;

    unsigned long long acc[2][4];
#pragma unroll
    for (int jp = 0; jp < 2; ++jp)
#pragma unroll
        for (int i = 0; i < 4; ++i) acc[jp][i] = 0ull;

#pragma unroll 2
    for (int c = 0; c < 128; ++c) {
        const float* xr = &xs[c*64 + wb];
        float4 xv = *reinterpret_cast<const float4*>(xr);
        float xm1 = (wb == 0) ? 0.f : xr[-1];
        float hv[5] = {xm1, xv.x, xv.y, xv.z, xv.w};
        unsigned long long hp[5];
#pragma unroll
        for (int t = 0; t < 5; ++t) PACK2(hp[t], hv[t], hv[t]);
#pragma unroll
        for (int jp = 0; jp < 2; ++jp) {
            unsigned long long w0p = *reinterpret_cast<const unsigned long long*>(&w0[c*64 + ty*4 + 2*jp]);
            unsigned long long w1p = *reinterpret_cast<const unsigned long long*>(&w1[c*64 + ty*4 + 2*jp]);
#pragma unroll
            for (int i = 0; i < 4; ++i) {
                FMA2(acc[jp][i], w0p, hp[i],   acc[jp][i]);
                FMA2(acc[jp][i], w1p, hp[i+1], acc[jp][i]);
            }
        }
    }

#pragma unroll
    for (int jp = 0; jp < 2; ++jp) {
        float lo[4], hi[4];
#pragma unroll
        for (int i = 0; i < 4; ++i) UNPK2(lo[i], hi[i], acc[jp][i]);
        int oA = o0 + ty*4 + 2*jp;
        float bA = bis[oA], bB = bis[oA+1];
        float4 rA = {lo[0]+bA, lo[1]+bA, lo[2]+bA, lo[3]+bA};
        float4 rB = {hi[0]+bB, hi[1]+bB, hi[2]+bB, hi[3]+bB};
        *reinterpret_cast<float4*>(&g_zis[(((size_t)b*OC + oA  )*Hh + h)*Ww + wb]) = rA;
        *reinterpret_cast<float4*>(&g_zis[(((size_t)b*OC + oA+1)*Hh + h)*Ww + wb]) = rB;
    }
}

// ---------------------------------------------------------------------------
// Phase 2: persistent fused recurrence, NO clusters.
// 128 CTAs; CTA (b, hb) owns o-channels { g*128 + hb*16 + l }, computes gates
// for hid channels hb*16..hb*16+15. h is exchanged through L2 (g_hbuf, double
// buffered) with a per-batch release/acquire counter barrier per row.
// hs layout: stride 72 floats/channel, h[w] at c*72 + 4 + w (halos stay 0).
#define HSTR 72
#define HS1  (128*HSTR)
__global__ void __launch_bounds__(256, 1)
kP_rows(const float* __restrict__ Wss,
        const float* __restrict__ bss,
        float* __restrict__ out) {
    extern __shared__ float sm[];
    float* wk   = sm;                    // [3][128][64]  24576 floats
    float* hs   = sm + 3*8192;           // [128][72]
    float* zbuf = hs + HS1;              // [64][66]

    int b   = blockIdx.x >> 3;
    int hb  = blockIdx.x & 7;
    int tid = threadIdx.x;
    int tx  = tid & 15, ty = tid >> 4;
    int wb  = tx * 4;

    unsigned* cnt = &g_cnt[b*32];

    // Load W_ss once: o_local = g*16 + l  ->  global o = g*128 + hb*16 + l
    for (int idx = tid; idx < 64*HID*3; idx += 256) {
        int ol  = idx / (HID*3);
        int rem = idx - ol*(HID*3);
        int g   = ol >> 4, l = ol & 15;
        int o   = g*128 + hb*16 + l;
        float v = Wss[(size_t)o*(HID*3) + rem];
        int c = rem / 3, k = rem - c*3;
        wk[k*8192 + c*64 + ol] = v;
    }
    // zero hs once (halo columns at +0..3 and +68..71 stay 0 forever)
    for (int idx = tid; idx < HS1; idx += 256) hs[idx] = 0.f;

    float sbv[4];
#pragma unroll
    for (int g = 0; g < 4; ++g) sbv[g] = bss[g*128 + hb*16 + ty];

    float cst[4] = {0.f, 0.f, 0.f, 0.f};
    int chg = hb*16 + ty;

    const float* zisb = g_zis + (size_t)b*OC*Hh*Ww;
    __syncthreads();

    for (int r = 0; r < Hh; ++r) {
        // prefetch z_is for the gate phase (independent of barrier -> overlaps poll)
        float4 ziv[4];
#pragma unroll
        for (int g = 0; g < 4; ++g)
            ziv[g] = *reinterpret_cast<const float4*>(
                &zisb[(((size_t)(g*128 + hb*16 + ty))*Hh + r)*Ww + wb]);

        unsigned long long acc[2][4];
#pragma unroll
        for (int jp = 0; jp < 2; ++jp)
#pragma unroll
            for (int i = 0; i < 4; ++i) acc[jp][i] = 0ull;

        if (r > 0) {
            // wait for all 8 CTAs of this b to have published row r-1
            if (tid == 0) {
                unsigned target = 8u * (unsigned)r;
                while (ld_acq_gpu(cnt) < target) __nanosleep(64);
            }
            __syncthreads();
            // reload h (float4, L2) into smem
            const float4* hsrc = reinterpret_cast<const float4*>(
                g_hbuf[(r-1) & 1] + b*HID*Ww);
#pragma unroll
            for (int it = 0; it < 8; ++it) {
                int j = tid + it*256;          // float4 index, 2048 total
                int c = j >> 4, w4 = (j & 15) * 4;
                float4 v = __ldcg(&hsrc[j]);
                *reinterpret_cast<float4*>(&hs[c*HSTR + 4 + w4]) = v;
            }
            __syncthreads();

#pragma unroll 2
            for (int c = 0; c < 128; ++c) {
                const float* hrow = &hs[c*HSTR + wb];
                float  hm1 = hrow[3];                                    // h[wb-1]
                float4 h03 = *reinterpret_cast<const float4*>(hrow + 4); // h[wb..wb+3]
                float  h4  = hrow[8];                                    // h[wb+4]
                float hv[6] = {hm1, h03.x, h03.y, h03.z, h03.w, h4};
                unsigned long long hp[6];
#pragma unroll
                for (int t = 0; t < 6; ++t) PACK2(hp[t], hv[t], hv[t]);
#pragma unroll
                for (int k = 0; k < 3; ++k) {
#pragma unroll
                    for (int jp = 0; jp < 2; ++jp) {
                        unsigned long long wp = *reinterpret_cast<const unsigned long long*>(
                            &wk[k*8192 + c*64 + ty*4 + 2*jp]);
#pragma unroll
                        for (int i = 0; i < 4; ++i)
                            FMA2(acc[jp][i], wp, hp[i+k], acc[jp][i]);
                    }
                }
            }
        }

        // stage z_ss into zbuf[w][o_local]
#pragma unroll
        for (int jp = 0; jp < 2; ++jp)
#pragma unroll
            for (int i = 0; i < 4; ++i)
                *reinterpret_cast<unsigned long long*>(
                    &zbuf[(wb + i)*66 + ty*4 + 2*jp]) = acc[jp][i];
        __syncthreads();

        // gates for (ch = chg, w = wb..wb+3)
        float4 hres;
#pragma unroll
        for (int i = 0; i < 4; ++i) {
            int w = wb + i;
            float zi = zbuf[w*66 +  0 + ty] + sbv[0] + (&ziv[0].x)[i];
            float zf = zbuf[w*66 + 16 + ty] + sbv[1] + (&ziv[1].x)[i];
            float zo = zbuf[w*66 + 32 + ty] + sbv[2] + (&ziv[2].x)[i];
            float zg = zbuf[w*66 + 48 + ty] + sbv[3] + (&ziv[3].x)[i];
            float ig = 1.f / (1.f + __expf(-zi));
            float fg = 1.f / (1.f + __expf(-zf));
            float og = 1.f / (1.f + __expf(-zo));
            float gg = tanhf(zg);
            float cn = fg*cst[i] + ig*gg;
            cst[i] = cn;
            (&hres.x)[i] = og * tanhf(cn);
        }
        *reinterpret_cast<float4*>(&out[(((size_t)b*HID + chg)*Hh + r)*Ww + wb]) = hres;

        if (r < Hh - 1) {
            // publish h_r, then release-arrive on the per-b counter
            __stcg(reinterpret_cast<float4*>(
                &g_hbuf[r & 1][(b*HID + chg)*Ww + wb]), hres);
            __syncthreads();               // all stcg done before the release
            if (tid == 0) red_rel_gpu(cnt, 1u);
        }
    }
}

// ---------------------------------------------------------------------------
extern "C" void kernel_launch(void* const* d_in, const int* in_sizes, int n_in,
                              void* d_out, int out_size) {
    const float* x   = (const float*)d_in[0];
    const float* Wis = (const float*)d_in[1];
    const float* bis = (const float*)d_in[2];
    const float* Wss = (const float*)d_in[3];
    const float* bss = (const float*)d_in[4];
    float* out = (float*)d_out;

    const int SMEM_A = 3*8192*sizeof(float);                     // 98304
    const int SMEM_P = (3*8192 + HS1 + 64*66)*sizeof(float);     // 152064
    cudaFuncSetAttribute(kA_zis,  cudaFuncAttributeMaxDynamicSharedMemorySize, SMEM_A);
    cudaFuncSetAttribute(kP_rows, cudaFuncAttributeMaxDynamicSharedMemorySize, SMEM_P);

    init_kernel<<<1, 512>>>();

    dim3 gA(Bb*Hh, OC/64);
    kA_zis<<<gA, 256, SMEM_A>>>(x, Wis, bis);

    kP_rows<<<NCTA, 256, SMEM_P>>>(Wss, bss, out);
}

// round 7
// speedup vs baseline: 1.4838x; 1.0765x over previous
#include <cuda_runtime.h>
#include <stdint.h>
#include <math.h>

#define Bb   16
#define Cc   128
#define Hh   64
#define Ww   64
#define HID  128
#define OC   512   // 4*HID
#define NCTA 128   // 16 b x 8 hid-blocks, all co-resident (<=148 SMs, 1 CTA/SM)

typedef unsigned long long u64;

// Scratch (device globals: allocation-free per harness rules)
__device__ float    g_zis[(size_t)Bb*OC*Hh*Ww];   // [b, o, h, w]  134 MB
__device__ float    g_hbuf[2][Bb*HID*Ww];         // double-buffered hidden state
__device__ unsigned g_cnt[16*32];                 // per-batch barrier counters (128B apart)

// ---- packed f32x2 helpers (sm_103a) --------------------------------------
#define PACK2(d, lo, hi) asm("mov.b64 %0, {%1,%2};" : "=l"(d) : "f"(lo), "f"(hi))
#define FMA2(d, a, b, c) asm("fma.rn.f32x2 %0, %1, %2, %3;" : "=l"(d) : "l"(a), "l"(b), "l"(c))
#define UNPK2(lo, hi, s) asm("mov.b64 {%0,%1}, %2;" : "=f"(lo), "=f"(hi) : "l"(s))

__device__ __forceinline__ unsigned ld_acq_gpu(const unsigned* p) {
    unsigned v;
    asm volatile("ld.global.acquire.gpu.u32 %0, [%1];" : "=r"(v) : "l"(p) : "memory");
    return v;
}
__device__ __forceinline__ void red_rel_gpu(unsigned* p, unsigned v) {
    asm volatile("red.release.gpu.global.add.u32 [%0], %1;" :: "l"(p), "r"(v) : "memory");
}

// ---------------------------------------------------------------------------
__global__ void init_kernel() {
    int i = threadIdx.x;
    if (i < 16*32) g_cnt[i] = 0u;
}

// ---------------------------------------------------------------------------
// Phase 1: masked input-to-state conv (taps k=0,1; k=2 masked away).
// grid (B*H, OC/64), block 512: tx=tid&15 (4 w each), typ=tid>>4 (o-pair 0..31).
// Weights staged pre-paired: wt[c][typ] = {k0_oe,k0_oo,k1_oe,k1_oo} (float4).
__global__ void __launch_bounds__(512)
kA_zis(const float* __restrict__ x,
       const float* __restrict__ Wis,
       const float* __restrict__ bis) {
    extern __shared__ float sm[];
    float* wt = sm;               // [c][32][4]   16384 floats
    float* xs = sm + 16384;       // [c][64]       8192 floats

    int b  = blockIdx.x >> 6;
    int h  = blockIdx.x & 63;
    int o0 = blockIdx.y * 64;
    int tid = threadIdx.x;

    for (int idx = tid; idx < 8192; idx += 512)
        xs[idx] = x[(((size_t)b*Cc + (idx >> 6))*Hh + h)*Ww + (idx & 63)];

    {   // coalesced weight read, scatter taps 0,1 into paired layout
        const float* wsrc = Wis + (size_t)o0 * (Cc*3);
        for (int idx = tid; idx < 64*Cc*3; idx += 512) {
            float v = wsrc[idx];
            int ol  = idx / (Cc*3);
            int rem = idx - ol*(Cc*3);
            int c   = rem / 3;
            int k   = rem - c*3;
            if (k < 2) wt[(c*32 + (ol >> 1))*4 + k*2 + (ol & 1)] = v;
        }
    }
    __syncthreads();

    int tx  = tid & 15;
    int typ = tid >> 4;            // o-pair index 0..31
    int wb  = tx * 4;

    u64 acc[4] = {0ull, 0ull, 0ull, 0ull};

#pragma unroll 2
    for (int c = 0; c < 128; ++c) {
        const float* xr = &xs[c*64 + wb];
        float4 xv = *reinterpret_cast<const float4*>(xr);
        float xm1 = (wb == 0) ? 0.f : xr[-1];
        float hv[5] = {xm1, xv.x, xv.y, xv.z, xv.w};
        u64 hp[5];
#pragma unroll
        for (int t = 0; t < 5; ++t) PACK2(hp[t], hv[t], hv[t]);
        ulonglong2 w01 = *reinterpret_cast<const ulonglong2*>(&wt[(c*32 + typ)*4]);
#pragma unroll
        for (int i = 0; i < 4; ++i) {
            FMA2(acc[i], w01.x, hp[i],   acc[i]);   // tap k=0 uses x[w-1]
            FMA2(acc[i], w01.y, hp[i+1], acc[i]);   // tap k=1 uses x[w]
        }
    }

    float lo[4], hi[4];
#pragma unroll
    for (int i = 0; i < 4; ++i) UNPK2(lo[i], hi[i], acc[i]);
    int oA = o0 + typ*2;
    float bA = bis[oA], bB = bis[oA+1];
    float4 rA = {lo[0]+bA, lo[1]+bA, lo[2]+bA, lo[3]+bA};
    float4 rB = {hi[0]+bB, hi[1]+bB, hi[2]+bB, hi[3]+bB};
    *reinterpret_cast<float4*>(&g_zis[(((size_t)b*OC + oA  )*Hh + h)*Ww + wb]) = rA;
    *reinterpret_cast<float4*>(&g_zis[(((size_t)b*OC + oA+1)*Hh + h)*Ww + wb]) = rB;
}

// ---------------------------------------------------------------------------
// Phase 2: persistent fused recurrence, 128 CTAs x 512 threads.
// CTA (b, hb) owns o-channels { g*128 + hb*16 + l : g 0..3, l 0..15 }.
// GEMM: tx=tid&15 (4 w), typ=tid>>4 (o-pair 0..31). Gates: cl=tid>>5, 2 w each.
// h exchanged through L2 (g_hbuf) with per-batch release/acquire counter.
#define HSTR 72
#define HS1  (128*HSTR)
__global__ void __launch_bounds__(512, 1)
kP_rows(const float* __restrict__ Wss,
        const float* __restrict__ bss,
        float* __restrict__ out) {
    extern __shared__ float sm[];
    float* wk01 = sm;                    // [c][32][4]  k0/k1 o-pairs, 16384 f
    float* wk2  = sm + 16384;            // [c][32][2]  k2 o-pairs,     8192 f
    float* hs   = wk2 + 8192;            // [128][72]  h[w] at c*72+4+w, 9216 f
    float* zbuf = hs + HS1;              // [64][66]                    4224 f

    int b   = blockIdx.x >> 3;
    int hb  = blockIdx.x & 7;
    int tid = threadIdx.x;
    int tx  = tid & 15;
    int typ = tid >> 4;                  // o-pair 0..31
    int wb  = tx * 4;

    unsigned* cnt = &g_cnt[b*32];

    // Load W_ss once: o_local = g*16 + l  ->  global o = g*128 + hb*16 + l
    for (int idx = tid; idx < 64*HID*3; idx += 512) {
        int ol  = idx / (HID*3);
        int rem = idx - ol*(HID*3);
        int g   = ol >> 4, l = ol & 15;
        int o   = g*128 + hb*16 + l;
        float v = Wss[(size_t)o*(HID*3) + rem];
        int c = rem / 3, k = rem - c*3;
        int pr = ol >> 1, ln = ol & 1;
        if (k < 2) wk01[(c*32 + pr)*4 + k*2 + ln] = v;
        else       wk2 [(c*32 + pr)*2 + ln] = v;
    }
    // zero hs once (halo columns at +0..3 and +68..71 stay 0 forever)
    for (int idx = tid; idx < HS1; idx += 512) hs[idx] = 0.f;

    // gate-phase mapping
    int cl = tid >> 5;                   // hid channel local 0..15
    int wg = (tid & 31) * 2;             // w pair base
    int chg = hb*16 + cl;

    float sbv[4];
#pragma unroll
    for (int g = 0; g < 4; ++g) sbv[g] = bss[g*128 + chg];

    float cst[2] = {0.f, 0.f};           // cell state (2 w per thread)

    const float* zisb = g_zis + (size_t)b*OC*Hh*Ww;
    __syncthreads();

    for (int r = 0; r < Hh; ++r) {
        // prefetch z_is for the gate phase (independent of barrier -> overlaps poll)
        float2 zv[4];
#pragma unroll
        for (int g = 0; g < 4; ++g)
            zv[g] = *reinterpret_cast<const float2*>(
                &zisb[(((size_t)(g*128 + chg))*Hh + r)*Ww + wg]);

        u64 acc[4] = {0ull, 0ull, 0ull, 0ull};

        if (r > 0) {
            // wait for all 8 CTAs of this b to have published row r-1
            if (tid == 0) {
                unsigned target = 8u * (unsigned)r;
                while (ld_acq_gpu(cnt) < target) __nanosleep(64);
            }
            __syncthreads();
            // reload h (float4, L2) into smem
            const float4* hsrc = reinterpret_cast<const float4*>(
                g_hbuf[(r-1) & 1] + b*HID*Ww);
#pragma unroll
            for (int it = 0; it < 4; ++it) {
                int j = tid + it*512;          // float4 index, 2048 total
                int c = j >> 4, w4 = (j & 15) * 4;
                float4 v = __ldcg(&hsrc[j]);
                *reinterpret_cast<float4*>(&hs[c*HSTR + 4 + w4]) = v;
            }
            __syncthreads();

#pragma unroll 2
            for (int c = 0; c < 128; ++c) {
                const float* hrow = &hs[c*HSTR + wb];
                float  hm1 = hrow[3];                                    // h[wb-1]
                float4 h03 = *reinterpret_cast<const float4*>(hrow + 4); // h[wb..wb+3]
                float  h4  = hrow[8];                                    // h[wb+4]
                float hv[6] = {hm1, h03.x, h03.y, h03.z, h03.w, h4};
                u64 hp[6];
#pragma unroll
                for (int t = 0; t < 6; ++t) PACK2(hp[t], hv[t], hv[t]);
                ulonglong2 w01 = *reinterpret_cast<const ulonglong2*>(&wk01[(c*32 + typ)*4]);
                u64        w2  = *reinterpret_cast<const u64*>(&wk2[(c*32 + typ)*2]);
#pragma unroll
                for (int i = 0; i < 4; ++i) {
                    FMA2(acc[i], w01.x, hp[i],   acc[i]);
                    FMA2(acc[i], w01.y, hp[i+1], acc[i]);
                    FMA2(acc[i], w2,    hp[i+2], acc[i]);
                }
            }
        }

        // stage z_ss into zbuf[w][o_local] (o pairs contiguous, 8B aligned)
#pragma unroll
        for (int i = 0; i < 4; ++i)
            *reinterpret_cast<u64*>(&zbuf[(wb + i)*66 + typ*2]) = acc[i];
        __syncthreads();

        // gates for (ch = chg, w = wg, wg+1)
        float2 hres;
#pragma unroll
        for (int j = 0; j < 2; ++j) {
            int w = wg + j;
            float zi = zbuf[w*66 +  0 + cl] + sbv[0] + (j ? zv[0].y : zv[0].x);
            float zf = zbuf[w*66 + 16 + cl] + sbv[1] + (j ? zv[1].y : zv[1].x);
            float zo = zbuf[w*66 + 32 + cl] + sbv[2] + (j ? zv[2].y : zv[2].x);
            float zg = zbuf[w*66 + 48 + cl] + sbv[3] + (j ? zv[3].y : zv[3].x);
            float ig = 1.f / (1.f + __expf(-zi));
            float fg = 1.f / (1.f + __expf(-zf));
            float og = 1.f / (1.f + __expf(-zo));
            float gg = tanhf(zg);
            float cn = fg*cst[j] + ig*gg;
            cst[j] = cn;
            (&hres.x)[j] = og * tanhf(cn);
        }
        *reinterpret_cast<float2*>(&out[(((size_t)b*HID + chg)*Hh + r)*Ww + wg]) = hres;

        if (r < Hh - 1) {
            // publish h_r, then release-arrive on the per-b counter
            __stcg(reinterpret_cast<float2*>(
                &g_hbuf[r & 1][(b*HID + chg)*Ww + wg]), hres);
            __syncthreads();               // all stcg done before the release
            if (tid == 0) red_rel_gpu(cnt, 1u);
        }
    }
}

// ---------------------------------------------------------------------------
extern "C" void kernel_launch(void* const* d_in, const int* in_sizes, int n_in,
                              void* d_out, int out_size) {
    const float* x   = (const float*)d_in[0];
    const float* Wis = (const float*)d_in[1];
    const float* bis = (const float*)d_in[2];
    const float* Wss = (const float*)d_in[3];
    const float* bss = (const float*)d_in[4];
    float* out = (float*)d_out;

    const int SMEM_A = (16384 + 8192)*sizeof(float);                    //  98304
    const int SMEM_P = (16384 + 8192 + HS1 + 64*66)*sizeof(float);      // 152064
    cudaFuncSetAttribute(kA_zis,  cudaFuncAttributeMaxDynamicSharedMemorySize, SMEM_A);
    cudaFuncSetAttribute(kP_rows, cudaFuncAttributeMaxDynamicSharedMemorySize, SMEM_P);

    init_kernel<<<1, 512>>>();

    dim3 gA(Bb*Hh, OC/64);
    kA_zis<<<gA, 512, SMEM_A>>>(x, Wis, bis);

    kP_rows<<<NCTA, 512, SMEM_P>>>(Wss, bss, out);
}

// round 8
// speedup vs baseline: 1.6888x; 1.1381x over previous
#include <cuda_runtime.h>
#include <stdint.h>
#include <math.h>

#define Bb   16
#define Cc   128
#define Hh   64
#define Ww   64
#define HID  128
#define OC   512   // 4*HID
#define NCTA 128   // 16 b x 8 hid-blocks, all co-resident (<=148 SMs, 1 CTA/SM)

typedef unsigned long long u64;

// Scratch (device globals: allocation-free per harness rules)
__device__ float    g_zis[(size_t)Bb*OC*Hh*Ww];   // [b, o, h, w]  134 MB
__device__ float    g_hbuf[2][Bb*HID*Ww];         // double-buffered hidden state
__device__ unsigned g_cnt[16*32];                 // per-batch barrier counters (128B apart)

// ---- packed f32x2 helpers (sm_103a) --------------------------------------
#define PACK2(d, lo, hi) asm("mov.b64 %0, {%1,%2};" : "=l"(d) : "f"(lo), "f"(hi))
#define FMA2(d, a, b, c) asm("fma.rn.f32x2 %0, %1, %2, %3;" : "=l"(d) : "l"(a), "l"(b), "l"(c))
#define UNPK2(lo, hi, s) asm("mov.b64 {%0,%1}, %2;" : "=f"(lo), "=f"(hi) : "l"(s))

__device__ __forceinline__ unsigned ld_acq_gpu(const unsigned* p) {
    unsigned v;
    asm volatile("ld.global.acquire.gpu.u32 %0, [%1];" : "=r"(v) : "l"(p) : "memory");
    return v;
}
__device__ __forceinline__ void red_rel_gpu(unsigned* p, unsigned v) {
    asm volatile("red.release.gpu.global.add.u32 [%0], %1;" :: "l"(p), "r"(v) : "memory");
}

// ---------------------------------------------------------------------------
__global__ void init_kernel() {
    int i = threadIdx.x;
    if (i < 16*32) g_cnt[i] = 0u;
}

// ---------------------------------------------------------------------------
// Phase 1: masked input-to-state conv (taps k=0,1; k=2 masked away).
// grid (B*H, OC/64), block 512: tx=tid&15 (4 w each), typ=tid>>4 (o-pair 0..31).
__global__ void __launch_bounds__(512)
kA_zis(const float* __restrict__ x,
       const float* __restrict__ Wis,
       const float* __restrict__ bis) {
    extern __shared__ float sm[];
    float* wt = sm;               // [c][32][4]   16384 floats
    float* xs = sm + 16384;       // [c][64]       8192 floats

    int b  = blockIdx.x >> 6;
    int h  = blockIdx.x & 63;
    int o0 = blockIdx.y * 64;
    int tid = threadIdx.x;

    for (int idx = tid; idx < 8192; idx += 512)
        xs[idx] = x[(((size_t)b*Cc + (idx >> 6))*Hh + h)*Ww + (idx & 63)];

    {   // coalesced weight read, scatter taps 0,1 into paired layout
        const float* wsrc = Wis + (size_t)o0 * (Cc*3);
        for (int idx = tid; idx < 64*Cc*3; idx += 512) {
            float v = wsrc[idx];
            int ol  = idx / (Cc*3);
            int rem = idx - ol*(Cc*3);
            int c   = rem / 3;
            int k   = rem - c*3;
            if (k < 2) wt[(c*32 + (ol >> 1))*4 + k*2 + (ol & 1)] = v;
        }
    }
    __syncthreads();

    int tx  = tid & 15;
    int typ = tid >> 4;            // o-pair index 0..31
    int wb  = tx * 4;

    u64 acc[4] = {0ull, 0ull, 0ull, 0ull};

#pragma unroll 2
    for (int c = 0; c < 128; ++c) {
        const float* xr = &xs[c*64 + wb];
        float4 xv = *reinterpret_cast<const float4*>(xr);
        float xm1 = (wb == 0) ? 0.f : xr[-1];
        float hv[5] = {xm1, xv.x, xv.y, xv.z, xv.w};
        u64 hp[5];
#pragma unroll
        for (int t = 0; t < 5; ++t) PACK2(hp[t], hv[t], hv[t]);
        ulonglong2 w01 = *reinterpret_cast<const ulonglong2*>(&wt[(c*32 + typ)*4]);
#pragma unroll
        for (int i = 0; i < 4; ++i) {
            FMA2(acc[i], w01.x, hp[i],   acc[i]);   // tap k=0 uses x[w-1]
            FMA2(acc[i], w01.y, hp[i+1], acc[i]);   // tap k=1 uses x[w]
        }
    }

    float lo[4], hi[4];
#pragma unroll
    for (int i = 0; i < 4; ++i) UNPK2(lo[i], hi[i], acc[i]);
    int oA = o0 + typ*2;
    float bA = bis[oA], bB = bis[oA+1];
    float4 rA = {lo[0]+bA, lo[1]+bA, lo[2]+bA, lo[3]+bA};
    float4 rB = {hi[0]+bB, hi[1]+bB, hi[2]+bB, hi[3]+bB};
    *reinterpret_cast<float4*>(&g_zis[(((size_t)b*OC + oA  )*Hh + h)*Ww + wb]) = rA;
    *reinterpret_cast<float4*>(&g_zis[(((size_t)b*OC + oA+1)*Hh + h)*Ww + wb]) = rB;
}

// ---------------------------------------------------------------------------
// Phase 2: persistent fused recurrence, 128 CTAs x 512 threads, K-SPLIT by 2.
// CTA (b, hb) owns o-channels { g*128 + hb*16 + l : g 0..3, l 0..15 }.
// GEMM: ks=tid>>8 (c-half), tx 4 w, ty 2 o-pairs; partials meet in zbuf[2].
// Gates: cl=tid>>5, 2 w each; h exchanged via L2 + per-batch counter barrier.
#define HSTR 72
#define HS1  (128*HSTR)
#define ZB1  (64*66)
__global__ void __launch_bounds__(512, 1)
kP_rows(const float* __restrict__ Wss,
        const float* __restrict__ bss,
        float* __restrict__ out) {
    extern __shared__ float sm[];
    float* wk01 = sm;                    // [c][32][4]  k0/k1 o-pairs, 16384 f
    float* wk2  = sm + 16384;            // [c][32][2]  k2 o-pairs,     8192 f
    float* hs   = wk2 + 8192;            // [128][72]  h[w] at c*72+4+w, 9216 f
    float* zbuf = hs + HS1;              // [2][64][66]                 8448 f

    int b   = blockIdx.x >> 3;
    int hb  = blockIdx.x & 7;
    int tid = threadIdx.x;
    int ks  = tid >> 8;                  // K-split half: c in [ks*64, ks*64+64)
    int t2  = tid & 255;
    int tx  = t2 & 15;
    int ty  = t2 >> 4;                   // o-quad 0..15 (o_local ty*4..ty*4+3)
    int wb  = tx * 4;

    unsigned* cnt = &g_cnt[b*32];

    // Load W_ss once: o_local = g*16 + l  ->  global o = g*128 + hb*16 + l
    for (int idx = tid; idx < 64*HID*3; idx += 512) {
        int ol  = idx / (HID*3);
        int rem = idx - ol*(HID*3);
        int g   = ol >> 4, l = ol & 15;
        int o   = g*128 + hb*16 + l;
        float v = Wss[(size_t)o*(HID*3) + rem];
        int c = rem / 3, k = rem - c*3;
        int pr = ol >> 1, ln = ol & 1;
        if (k < 2) wk01[(c*32 + pr)*4 + k*2 + ln] = v;
        else       wk2 [(c*32 + pr)*2 + ln] = v;
    }
    // zero hs once (halo columns at +0..3 and +68..71 stay 0 forever)
    for (int idx = tid; idx < HS1; idx += 512) hs[idx] = 0.f;

    // gate-phase mapping
    int cl = tid >> 5;                   // hid channel local 0..15
    int wg = (tid & 31) * 2;             // w pair base
    int chg = hb*16 + cl;

    float sbv[4];
#pragma unroll
    for (int g = 0; g < 4; ++g) sbv[g] = bss[g*128 + chg];

    float cst[2] = {0.f, 0.f};           // cell state (2 w per thread)

    const float* zisb = g_zis + (size_t)b*OC*Hh*Ww;
    const int cbase = ks * 64;
    const int pr0 = ty * 2, pr1 = ty * 2 + 1;
    __syncthreads();

    for (int r = 0; r < Hh; ++r) {
        // prefetch z_is for the gate phase (independent of barrier -> overlaps poll)
        float2 zv[4];
#pragma unroll
        for (int g = 0; g < 4; ++g)
            zv[g] = *reinterpret_cast<const float2*>(
                &zisb[(((size_t)(g*128 + chg))*Hh + r)*Ww + wg]);

        u64 acc[2][4] = {{0ull,0ull,0ull,0ull},{0ull,0ull,0ull,0ull}};

        if (r > 0) {
            // wait for all 8 CTAs of this b to have published row r-1
            if (tid == 0) {
                unsigned target = 8u * (unsigned)r;
                while (ld_acq_gpu(cnt) < target) __nanosleep(64);
            }
            __syncthreads();
            // reload h (float4, L2) into smem
            const float4* hsrc = reinterpret_cast<const float4*>(
                g_hbuf[(r-1) & 1] + b*HID*Ww);
#pragma unroll
            for (int it = 0; it < 4; ++it) {
                int j = tid + it*512;          // float4 index, 2048 total
                int c = j >> 4, w4 = (j & 15) * 4;
                float4 v = __ldcg(&hsrc[j]);
                *reinterpret_cast<float4*>(&hs[c*HSTR + 4 + w4]) = v;
            }
            __syncthreads();

#pragma unroll 2
            for (int cc = 0; cc < 64; ++cc) {
                int c = cbase + cc;
                const float* hrow = &hs[c*HSTR + wb];
                float  hm1 = hrow[3];                                    // h[wb-1]
                float4 h03 = *reinterpret_cast<const float4*>(hrow + 4); // h[wb..wb+3]
                float  h4  = hrow[8];                                    // h[wb+4]
                float hv[6] = {hm1, h03.x, h03.y, h03.z, h03.w, h4};
                u64 hp[6];
#pragma unroll
                for (int t = 0; t < 6; ++t) PACK2(hp[t], hv[t], hv[t]);
                ulonglong2 wA = *reinterpret_cast<const ulonglong2*>(&wk01[(c*32 + pr0)*4]);
                ulonglong2 wB = *reinterpret_cast<const ulonglong2*>(&wk01[(c*32 + pr1)*4]);
                u64 w2A = *reinterpret_cast<const u64*>(&wk2[(c*32 + pr0)*2]);
                u64 w2B = *reinterpret_cast<const u64*>(&wk2[(c*32 + pr1)*2]);
#pragma unroll
                for (int i = 0; i < 4; ++i) {
                    FMA2(acc[0][i], wA.x, hp[i],   acc[0][i]);
                    FMA2(acc[0][i], wA.y, hp[i+1], acc[0][i]);
                    FMA2(acc[0][i], w2A,  hp[i+2], acc[0][i]);
                    FMA2(acc[1][i], wB.x, hp[i],   acc[1][i]);
                    FMA2(acc[1][i], wB.y, hp[i+1], acc[1][i]);
                    FMA2(acc[1][i], w2B,  hp[i+2], acc[1][i]);
                }
            }
        }

        // stage partial z_ss into zbuf[ks][w][o_local] (o pairs contiguous)
        float* zb = zbuf + ks*ZB1;
#pragma unroll
        for (int i = 0; i < 4; ++i) {
            *reinterpret_cast<u64*>(&zb[(wb + i)*66 + pr0*2]) = acc[0][i];
            *reinterpret_cast<u64*>(&zb[(wb + i)*66 + pr1*2]) = acc[1][i];
        }
        __syncthreads();

        // gates for (ch = chg, w = wg, wg+1); z = partialA + partialB
        float2 hres;
#pragma unroll
        for (int j = 0; j < 2; ++j) {
            int w = wg + j;
            float zi = zbuf[w*66 +  0 + cl] + zbuf[ZB1 + w*66 +  0 + cl] + sbv[0] + (j ? zv[0].y : zv[0].x);
            float zf = zbuf[w*66 + 16 + cl] + zbuf[ZB1 + w*66 + 16 + cl] + sbv[1] + (j ? zv[1].y : zv[1].x);
            float zo = zbuf[w*66 + 32 + cl] + zbuf[ZB1 + w*66 + 32 + cl] + sbv[2] + (j ? zv[2].y : zv[2].x);
            float zg = zbuf[w*66 + 48 + cl] + zbuf[ZB1 + w*66 + 48 + cl] + sbv[3] + (j ? zv[3].y : zv[3].x);
            float ig = 1.f / (1.f + __expf(-zi));
            float fg = 1.f / (1.f + __expf(-zf));
            float og = 1.f / (1.f + __expf(-zo));
            float gg = tanhf(zg);
            float cn = fg*cst[j] + ig*gg;
            cst[j] = cn;
            (&hres.x)[j] = og * tanhf(cn);
        }
        *reinterpret_cast<float2*>(&out[(((size_t)b*HID + chg)*Hh + r)*Ww + wg]) = hres;

        if (r < Hh - 1) {
            // publish h_r, then release-arrive on the per-b counter
            __stcg(reinterpret_cast<float2*>(
                &g_hbuf[r & 1][(b*HID + chg)*Ww + wg]), hres);
            __syncthreads();               // all stcg done before the release
            if (tid == 0) red_rel_gpu(cnt, 1u);
        }
    }
}

// ---------------------------------------------------------------------------
extern "C" void kernel_launch(void* const* d_in, const int* in_sizes, int n_in,
                              void* d_out, int out_size) {
    const float* x   = (const float*)d_in[0];
    const float* Wis = (const float*)d_in[1];
    const float* bis = (const float*)d_in[2];
    const float* Wss = (const float*)d_in[3];
    const float* bss = (const float*)d_in[4];
    float* out = (float*)d_out;

    const int SMEM_A = (16384 + 8192)*sizeof(float);                    //  98304
    const int SMEM_P = (16384 + 8192 + HS1 + 2*ZB1)*sizeof(float);      // 168960
    cudaFuncSetAttribute(kA_zis,  cudaFuncAttributeMaxDynamicSharedMemorySize, SMEM_A);
    cudaFuncSetAttribute(kP_rows, cudaFuncAttributeMaxDynamicSharedMemorySize, SMEM_P);

    init_kernel<<<1, 512>>>();

    dim3 gA(Bb*Hh, OC/64);
    kA_zis<<<gA, 512, SMEM_A>>>(x, Wis, bis);

    kP_rows<<<NCTA, 512, SMEM_P>>>(Wss, bss, out);
}